// round 10
// baseline (speedup 1.0000x reference)
#include <cuda_runtime.h>
#include <cuda_bf16.h>

#define HIDDEN 256
#define HEADS 8
#define HEAD_DIM 32
#define NROWS 4096
#define LN_EPS 1e-5f
#define SCALE 0.17677669529663687f  // 32^-0.5

// ---------------- scratch (no allocation allowed) ----------------
__device__ float g_h[NROWS * HIDDEN];
__device__ float g_q[NROWS * HIDDEN];
__device__ float g_k[NROWS * HIDDEN];
__device__ float g_v[NROWS * HIDDEN];
__device__ float g_att[NROWS * HIDDEN];

// ---------------- LayerNorm: one block per row ----------------
__global__ void ln_kernel(const float* __restrict__ x,
                          const float* __restrict__ gamma,
                          const float* __restrict__ beta,
                          float* __restrict__ h)
{
    int i = blockIdx.x;
    int t = threadIdx.x;          // 256 threads, one element each
    __shared__ float red1[8];
    __shared__ float red2[8];

    float val = x[i * HIDDEN + t];

    float s = val;
    #pragma unroll
    for (int o = 16; o > 0; o >>= 1) s += __shfl_xor_sync(0xffffffffu, s, o);
    if ((t & 31) == 0) red1[t >> 5] = s;
    __syncthreads();
    float mean = 0.f;
    #pragma unroll
    for (int q = 0; q < 8; q++) mean += red1[q];
    mean *= (1.0f / HIDDEN);

    float dv = val - mean;
    float s2 = dv * dv;
    #pragma unroll
    for (int o = 16; o > 0; o >>= 1) s2 += __shfl_xor_sync(0xffffffffu, s2, o);
    if ((t & 31) == 0) red2[t >> 5] = s2;
    __syncthreads();
    float var = 0.f;
    #pragma unroll
    for (int q = 0; q < 8; q++) var += red2[q];
    var *= (1.0f / HIDDEN);

    h[i * HIDDEN + t] = dv * rsqrtf(var + LN_EPS) * gamma[t] + beta[t];
}

// ---------------- Tiled fp32 GEMM: C[M,N] = A[M,K] @ W[K,N] + bias (+ residual) ----------------
#define BM 64
#define BN 64
#define BK 16
#define TM 4
#define TN 4

__global__ void gemm_bias(const float* __restrict__ A,
                          const float* __restrict__ W,
                          const float* __restrict__ bias,
                          const float* __restrict__ residual,   // may be nullptr
                          float* __restrict__ C,
                          int M, int N, int K)
{
    __shared__ float As[BK][BM];   // transposed A tile
    __shared__ float Bs[BK][BN];

    int bm = blockIdx.y * BM;
    int bn = blockIdx.x * BN;
    int tid = threadIdx.x;          // 256 threads
    int tx = tid & 15;
    int ty = tid >> 4;

    // A tile load: 64 rows x 16 cols -> 256 float4, one per thread
    int arow  = tid >> 2;           // 0..63
    int acol4 = (tid & 3) * 4;      // 0,4,8,12
    // B tile load: 16 rows x 64 cols -> 256 float4, one per thread
    int brow  = tid >> 4;           // 0..15
    int bcol4 = (tid & 15) * 4;

    float acc[TM][TN];
    #pragma unroll
    for (int i = 0; i < TM; i++)
        #pragma unroll
        for (int j = 0; j < TN; j++) acc[i][j] = 0.f;

    for (int k0 = 0; k0 < K; k0 += BK) {
        float4 a = *(const float4*)&A[(bm + arow) * K + k0 + acol4];
        As[acol4 + 0][arow] = a.x;
        As[acol4 + 1][arow] = a.y;
        As[acol4 + 2][arow] = a.z;
        As[acol4 + 3][arow] = a.w;
        float4 b = *(const float4*)&W[(k0 + brow) * N + bn + bcol4];
        *(float4*)&Bs[brow][bcol4] = b;
        __syncthreads();

        #pragma unroll
        for (int kk = 0; kk < BK; kk++) {
            float ar[TM], br[TN];
            #pragma unroll
            for (int i = 0; i < TM; i++) ar[i] = As[kk][ty * TM + i];
            #pragma unroll
            for (int j = 0; j < TN; j++) br[j] = Bs[kk][tx * TN + j];
            #pragma unroll
            for (int i = 0; i < TM; i++)
                #pragma unroll
                for (int j = 0; j < TN; j++)
                    acc[i][j] = fmaf(ar[i], br[j], acc[i][j]);
        }
        __syncthreads();
    }

    #pragma unroll
    for (int i = 0; i < TM; i++) {
        int row = bm + ty * TM + i;
        #pragma unroll
        for (int j = 0; j < TN; j++) {
            int col = bn + tx * TN + j;
            float val = acc[i][j] + bias[col];
            if (residual) val += residual[row * N + col];
            C[row * N + col] = val;
        }
    }
}

// ---------------- Block-diagonal attention ----------------
// 1 block per row; 8 warps = 8 heads; lane = head-dim element.
// Online softmax over the row's same-graph segment (batch is sorted, int32).
__global__ void attn_kernel(const float* __restrict__ q,
                            const float* __restrict__ k,
                            const float* __restrict__ v,
                            const int* __restrict__ batch,
                            float* __restrict__ out)
{
    int i = blockIdx.x;
    int w = threadIdx.x >> 5;   // head
    int d = threadIdx.x & 31;   // dim within head

    __shared__ int s_start, s_end;
    if (threadIdx.x == 0) {
        int b = batch[i];
        int lo = 0, hi = NROWS;
        while (lo < hi) { int mid = (lo + hi) >> 1; if (batch[mid] <  b) lo = mid + 1; else hi = mid; }
        s_start = lo;
        lo = 0; hi = NROWS;
        while (lo < hi) { int mid = (lo + hi) >> 1; if (batch[mid] <= b) lo = mid + 1; else hi = mid; }
        s_end = lo;
    }
    __syncthreads();
    int s0 = s_start, e0 = s_end;

    int base = w * HEAD_DIM + d;
    float qv = q[i * HIDDEN + base] * SCALE;

    const float* kp = k + base + (size_t)s0 * HIDDEN;
    const float* vp = v + base + (size_t)s0 * HIDDEN;

    float m = -1e30f, l = 0.f, acc = 0.f;
    for (int j = s0; j < e0; j++) {
        float kv = __ldg(kp);
        float vv = __ldg(vp);
        kp += HIDDEN; vp += HIDDEN;
        float s = qv * kv;
        #pragma unroll
        for (int o = 16; o > 0; o >>= 1) s += __shfl_xor_sync(0xffffffffu, s, o);
        float mn = fmaxf(m, s);
        float co = __expf(m - mn);
        float p  = __expf(s - mn);
        l = l * co + p;
        acc = acc * co + p * vv;
        m = mn;
    }
    out[i * HIDDEN + base] = (l > 0.f) ? (acc / l) : 0.f;
}

// ---------------- launch ----------------
extern "C" void kernel_launch(void* const* d_in, const int* in_sizes, int n_in,
                              void* d_out, int out_size)
{
    const float* x     = (const float*)d_in[0];
    const int*   batch = (const int*)d_in[1];   // int32! (JAX x64 disabled downcasts int64)
    const float* Wq = (const float*)d_in[2];
    const float* bq = (const float*)d_in[3];
    const float* Wk = (const float*)d_in[4];
    const float* bk = (const float*)d_in[5];
    const float* Wv = (const float*)d_in[6];
    const float* bv = (const float*)d_in[7];
    const float* Wo = (const float*)d_in[8];
    const float* bo = (const float*)d_in[9];
    const float* gamma = (const float*)d_in[10];
    const float* beta  = (const float*)d_in[11];
    float* out = (float*)d_out;

    float *h_p, *q_p, *k_p, *v_p, *att_p;
    cudaGetSymbolAddress((void**)&h_p,  g_h);
    cudaGetSymbolAddress((void**)&q_p,  g_q);
    cudaGetSymbolAddress((void**)&k_p,  g_k);
    cudaGetSymbolAddress((void**)&v_p,  g_v);
    cudaGetSymbolAddress((void**)&att_p, g_att);

    ln_kernel<<<NROWS, 256>>>(x, gamma, beta, h_p);

    dim3 gg(HIDDEN / BN, NROWS / BM);
    gemm_bias<<<gg, 256>>>(h_p, Wq, bq, nullptr, q_p, NROWS, HIDDEN, HIDDEN);
    gemm_bias<<<gg, 256>>>(h_p, Wk, bk, nullptr, k_p, NROWS, HIDDEN, HIDDEN);
    gemm_bias<<<gg, 256>>>(h_p, Wv, bv, nullptr, v_p, NROWS, HIDDEN, HIDDEN);

    attn_kernel<<<NROWS, 256>>>(q_p, k_p, v_p, batch, att_p);

    gemm_bias<<<gg, 256>>>(att_p, Wo, bo, x, out, NROWS, HIDDEN, HIDDEN);
}

// round 12
// speedup vs baseline: 1.6702x; 1.6702x over previous
#include <cuda_runtime.h>
#include <cuda_bf16.h>

#define HIDDEN 256
#define HEADS 8
#define HEAD_DIM 32
#define NROWS 4096
#define NGRAPH 16
#define LN_EPS 1e-5f
#define SCALE 0.17677669529663687f  // 32^-0.5

// ---------------- scratch (no allocation allowed) ----------------
__device__ float g_h[NROWS * HIDDEN];
__device__ float g_q[NROWS * HIDDEN];
__device__ float g_k[NROWS * HIDDEN];
__device__ float g_v[NROWS * HIDDEN];
__device__ float g_att[NROWS * HIDDEN];

// ---------------- LayerNorm: one block per row ----------------
__global__ void ln_kernel(const float* __restrict__ x,
                          const float* __restrict__ gamma,
                          const float* __restrict__ beta,
                          float* __restrict__ h)
{
    int i = blockIdx.x;
    int t = threadIdx.x;          // 256 threads, one element each
    __shared__ float red1[8];
    __shared__ float red2[8];

    float val = x[i * HIDDEN + t];

    float s = val;
    #pragma unroll
    for (int o = 16; o > 0; o >>= 1) s += __shfl_xor_sync(0xffffffffu, s, o);
    if ((t & 31) == 0) red1[t >> 5] = s;
    __syncthreads();
    float mean = 0.f;
    #pragma unroll
    for (int q = 0; q < 8; q++) mean += red1[q];
    mean *= (1.0f / HIDDEN);

    float dv = val - mean;
    float s2 = dv * dv;
    #pragma unroll
    for (int o = 16; o > 0; o >>= 1) s2 += __shfl_xor_sync(0xffffffffu, s2, o);
    if ((t & 31) == 0) red2[t >> 5] = s2;
    __syncthreads();
    float var = 0.f;
    #pragma unroll
    for (int q = 0; q < 8; q++) var += red2[q];
    var *= (1.0f / HIDDEN);

    h[i * HIDDEN + t] = dv * rsqrtf(var + LN_EPS) * gamma[t] + beta[t];
}

// ---------------- Tiled fp32 GEMM core ----------------
#define BM 64
#define BN 64
#define BK 16
#define TM 4
#define TN 4

__device__ __forceinline__ void gemm_tile(const float* __restrict__ A,
                                          const float* __restrict__ W,
                                          const float* __restrict__ bias,
                                          const float* __restrict__ residual,
                                          float* __restrict__ C,
                                          int K, int N, int bm, int bn)
{
    __shared__ float As[BK][BM];   // transposed A tile
    __shared__ float Bs[BK][BN];

    int tid = threadIdx.x;          // 256 threads
    int tx = tid & 15;
    int ty = tid >> 4;

    int arow  = tid >> 2;           // 0..63
    int acol4 = (tid & 3) * 4;      // 0,4,8,12
    int brow  = tid >> 4;           // 0..15
    int bcol4 = (tid & 15) * 4;

    float acc[TM][TN];
    #pragma unroll
    for (int i = 0; i < TM; i++)
        #pragma unroll
        for (int j = 0; j < TN; j++) acc[i][j] = 0.f;

    for (int k0 = 0; k0 < K; k0 += BK) {
        float4 a = *(const float4*)&A[(bm + arow) * K + k0 + acol4];
        As[acol4 + 0][arow] = a.x;
        As[acol4 + 1][arow] = a.y;
        As[acol4 + 2][arow] = a.z;
        As[acol4 + 3][arow] = a.w;
        float4 b = *(const float4*)&W[(k0 + brow) * N + bn + bcol4];
        *(float4*)&Bs[brow][bcol4] = b;
        __syncthreads();

        #pragma unroll
        for (int kk = 0; kk < BK; kk++) {
            float ar[TM], br[TN];
            #pragma unroll
            for (int i = 0; i < TM; i++) ar[i] = As[kk][ty * TM + i];
            #pragma unroll
            for (int j = 0; j < TN; j++) br[j] = Bs[kk][tx * TN + j];
            #pragma unroll
            for (int i = 0; i < TM; i++)
                #pragma unroll
                for (int j = 0; j < TN; j++)
                    acc[i][j] = fmaf(ar[i], br[j], acc[i][j]);
        }
        __syncthreads();
    }

    #pragma unroll
    for (int i = 0; i < TM; i++) {
        int row = bm + ty * TM + i;
        #pragma unroll
        for (int j = 0; j < TN; j++) {
            int col = bn + tx * TN + j;
            float val = acc[i][j] + bias[col];
            if (residual) val += residual[row * N + col];
            C[row * N + col] = val;
        }
    }
}

// Fused QKV GEMM: blockIdx.z selects {q,k,v}. 768 blocks -> much better occupancy.
__global__ void gemm_qkv(const float* __restrict__ A,
                         const float* __restrict__ Wq, const float* __restrict__ bq, float* __restrict__ Cq,
                         const float* __restrict__ Wk, const float* __restrict__ bk, float* __restrict__ Ck,
                         const float* __restrict__ Wv, const float* __restrict__ bv, float* __restrict__ Cv)
{
    const float* W; const float* bias; float* C;
    if (blockIdx.z == 0)      { W = Wq; bias = bq; C = Cq; }
    else if (blockIdx.z == 1) { W = Wk; bias = bk; C = Ck; }
    else                      { W = Wv; bias = bv; C = Cv; }
    gemm_tile(A, W, bias, nullptr, C, HIDDEN, HIDDEN, blockIdx.y * BM, blockIdx.x * BN);
}

__global__ void gemm_out(const float* __restrict__ A,
                         const float* __restrict__ W,
                         const float* __restrict__ bias,
                         const float* __restrict__ residual,
                         float* __restrict__ C)
{
    gemm_tile(A, W, bias, residual, C, HIDDEN, HIDDEN, blockIdx.y * BM, blockIdx.x * BN);
}

// ---------------- Block-diagonal attention, per-(graph, head) block ----------------
// 256 threads; thread = one query row (looped if segment > 256).
// K/V tiles staged in shared, broadcast-read. No shuffles; 64 FMA/key.
#define CHUNK 128

__global__ void attn_kernel(const float* __restrict__ q,
                            const float* __restrict__ k,
                            const float* __restrict__ v,
                            const int* __restrict__ batch,
                            float* __restrict__ out)
{
    __shared__ float sK[CHUNK][HEAD_DIM];
    __shared__ float sV[CHUNK][HEAD_DIM];
    __shared__ int sBounds[2];

    int g = blockIdx.x;      // graph id
    int h = blockIdx.y;      // head
    int t = threadIdx.x;     // 0..255

    if (t == 0) {
        int lo = 0, hi = NROWS;
        while (lo < hi) { int mid = (lo + hi) >> 1; if (batch[mid] <  g) lo = mid + 1; else hi = mid; }
        sBounds[0] = lo;
        int lo2 = lo; hi = NROWS;
        while (lo2 < hi) { int mid = (lo2 + hi) >> 1; if (batch[mid] <= g) lo2 = mid + 1; else hi = mid; }
        sBounds[1] = lo2;
    }
    __syncthreads();
    int s0 = sBounds[0], e0 = sBounds[1];
    if (s0 >= e0) return;    // graph id absent

    int hbase = h * HEAD_DIM;

    for (int q0 = s0; q0 < e0; q0 += 256) {
        int qi = q0 + t;
        bool active = (qi < e0);

        float4 qv[8];
        if (active) {
            const float4* qp = (const float4*)(q + (size_t)qi * HIDDEN + hbase);
            #pragma unroll
            for (int i = 0; i < 8; i++) {
                float4 x4 = qp[i];
                x4.x *= SCALE; x4.y *= SCALE; x4.z *= SCALE; x4.w *= SCALE;
                qv[i] = x4;
            }
        }
        float m = -1e30f, l = 0.f;
        float4 acc[8];
        #pragma unroll
        for (int i = 0; i < 8; i++) acc[i] = make_float4(0.f, 0.f, 0.f, 0.f);

        for (int c0 = s0; c0 < e0; c0 += CHUNK) {
            int cn = min(CHUNK, e0 - c0);
            __syncthreads();
            for (int idx = t; idx < cn * 8; idx += 256) {
                int row = idx >> 3, c4 = idx & 7;
                size_t goff = (size_t)(c0 + row) * HIDDEN + hbase + c4 * 4;
                ((float4*)sK[row])[c4] = *(const float4*)(k + goff);
                ((float4*)sV[row])[c4] = *(const float4*)(v + goff);
            }
            __syncthreads();

            if (active) {
                for (int j = 0; j < cn; j++) {
                    const float4* kr = (const float4*)sK[j];
                    // 4-way split dot product (break the FFMA dependency chain)
                    float p0 = 0.f, p1 = 0.f, p2 = 0.f, p3 = 0.f;
                    #pragma unroll
                    for (int i = 0; i < 8; i++) {
                        float4 k4 = kr[i];
                        p0 = fmaf(qv[i].x, k4.x, p0);
                        p1 = fmaf(qv[i].y, k4.y, p1);
                        p2 = fmaf(qv[i].z, k4.z, p2);
                        p3 = fmaf(qv[i].w, k4.w, p3);
                    }
                    float s = (p0 + p1) + (p2 + p3);
                    const float4* vr = (const float4*)sV[j];
                    if (s <= m) {
                        float p = __expf(s - m);
                        l += p;
                        #pragma unroll
                        for (int i = 0; i < 8; i++) {
                            float4 v4 = vr[i];
                            acc[i].x = fmaf(p, v4.x, acc[i].x);
                            acc[i].y = fmaf(p, v4.y, acc[i].y);
                            acc[i].z = fmaf(p, v4.z, acc[i].z);
                            acc[i].w = fmaf(p, v4.w, acc[i].w);
                        }
                    } else {
                        float co = __expf(m - s);
                        m = s;
                        l = fmaf(l, co, 1.f);
                        #pragma unroll
                        for (int i = 0; i < 8; i++) {
                            float4 v4 = vr[i];
                            acc[i].x = fmaf(acc[i].x, co, v4.x);
                            acc[i].y = fmaf(acc[i].y, co, v4.y);
                            acc[i].z = fmaf(acc[i].z, co, v4.z);
                            acc[i].w = fmaf(acc[i].w, co, v4.w);
                        }
                    }
                }
            }
        }

        if (active) {
            float inv = 1.f / l;
            float4* op = (float4*)(out + (size_t)qi * HIDDEN + hbase);
            #pragma unroll
            for (int i = 0; i < 8; i++) {
                float4 a4 = acc[i];
                a4.x *= inv; a4.y *= inv; a4.z *= inv; a4.w *= inv;
                op[i] = a4;
            }
        }
    }
}

// ---------------- launch ----------------
extern "C" void kernel_launch(void* const* d_in, const int* in_sizes, int n_in,
                              void* d_out, int out_size)
{
    const float* x     = (const float*)d_in[0];
    const int*   batch = (const int*)d_in[1];   // int32 (JAX x64 disabled)
    const float* Wq = (const float*)d_in[2];
    const float* bq = (const float*)d_in[3];
    const float* Wk = (const float*)d_in[4];
    const float* bk = (const float*)d_in[5];
    const float* Wv = (const float*)d_in[6];
    const float* bv = (const float*)d_in[7];
    const float* Wo = (const float*)d_in[8];
    const float* bo = (const float*)d_in[9];
    const float* gamma = (const float*)d_in[10];
    const float* beta  = (const float*)d_in[11];
    float* out = (float*)d_out;

    float *h_p, *q_p, *k_p, *v_p, *att_p;
    cudaGetSymbolAddress((void**)&h_p,  g_h);
    cudaGetSymbolAddress((void**)&q_p,  g_q);
    cudaGetSymbolAddress((void**)&k_p,  g_k);
    cudaGetSymbolAddress((void**)&v_p,  g_v);
    cudaGetSymbolAddress((void**)&att_p, g_att);

    ln_kernel<<<NROWS, 256>>>(x, gamma, beta, h_p);

    dim3 gqkv(HIDDEN / BN, NROWS / BM, 3);
    gemm_qkv<<<gqkv, 256>>>(h_p, Wq, bq, q_p, Wk, bk, k_p, Wv, bv, v_p);

    dim3 ga(NGRAPH, HEADS);
    attn_kernel<<<ga, 256>>>(q_p, k_p, v_p, batch, att_p);

    dim3 gg(HIDDEN / BN, NROWS / BM);
    gemm_out<<<gg, 256>>>(att_p, Wo, bo, x, out);
}

// round 14
// speedup vs baseline: 2.1569x; 1.2914x over previous
#include <cuda_runtime.h>
#include <cuda_bf16.h>

#define HIDDEN 256
#define HEADS 8
#define HEAD_DIM 32
#define NROWS 4096
#define NGRAPH 16
#define LN_EPS 1e-5f
#define SCALE 0.17677669529663687f  // 32^-0.5

// ---------------- scratch (no allocation allowed) ----------------
__device__ float g_h[NROWS * HIDDEN];
__device__ float g_q[NROWS * HIDDEN];
__device__ float g_k[NROWS * HIDDEN];
__device__ float g_v[NROWS * HIDDEN];
__device__ float g_att[NROWS * HIDDEN];

// ---------------- LayerNorm: one block per row ----------------
__global__ void ln_kernel(const float* __restrict__ x,
                          const float* __restrict__ gamma,
                          const float* __restrict__ beta,
                          float* __restrict__ h)
{
    int i = blockIdx.x;
    int t = threadIdx.x;          // 256 threads, one element each
    __shared__ float red1[8];
    __shared__ float red2[8];

    float val = x[i * HIDDEN + t];

    float s = val;
    #pragma unroll
    for (int o = 16; o > 0; o >>= 1) s += __shfl_xor_sync(0xffffffffu, s, o);
    if ((t & 31) == 0) red1[t >> 5] = s;
    __syncthreads();
    float mean = 0.f;
    #pragma unroll
    for (int q = 0; q < 8; q++) mean += red1[q];
    mean *= (1.0f / HIDDEN);

    float dv = val - mean;
    float s2 = dv * dv;
    #pragma unroll
    for (int o = 16; o > 0; o >>= 1) s2 += __shfl_xor_sync(0xffffffffu, s2, o);
    if ((t & 31) == 0) red2[t >> 5] = s2;
    __syncthreads();
    float var = 0.f;
    #pragma unroll
    for (int q = 0; q < 8; q++) var += red2[q];
    var *= (1.0f / HIDDEN);

    h[i * HIDDEN + t] = dv * rsqrtf(var + LN_EPS) * gamma[t] + beta[t];
}

// ---------------- Double-buffered fp32 GEMM core ----------------
#define BM 64
#define BN 64
#define BK 16
#define TM 4
#define TN 4

__device__ __forceinline__ void gemm_tile_db(const float* __restrict__ A,
                                             const float* __restrict__ W,
                                             const float* __restrict__ bias,
                                             const float* __restrict__ residual,
                                             float* __restrict__ C,
                                             int bm, int bn)
{
    const int K = HIDDEN, N = HIDDEN;
    __shared__ float As[2][BK][BM];   // transposed A tile
    __shared__ float Bs[2][BK][BN];

    int tid = threadIdx.x;          // 256 threads
    int tx = tid & 15;
    int ty = tid >> 4;

    int arow  = tid >> 2;           // 0..63
    int acol4 = (tid & 3) * 4;      // 0,4,8,12
    int brow  = tid >> 4;           // 0..15
    int bcol4 = (tid & 15) * 4;

    float acc[TM][TN];
    #pragma unroll
    for (int i = 0; i < TM; i++)
        #pragma unroll
        for (int j = 0; j < TN; j++) acc[i][j] = 0.f;

    // preload tile 0
    float4 a = *(const float4*)&A[(bm + arow) * K + acol4];
    float4 b = *(const float4*)&W[brow * N + bn + bcol4];
    As[0][acol4 + 0][arow] = a.x;
    As[0][acol4 + 1][arow] = a.y;
    As[0][acol4 + 2][arow] = a.z;
    As[0][acol4 + 3][arow] = a.w;
    *(float4*)&Bs[0][brow][bcol4] = b;
    __syncthreads();

    int buf = 0;
    for (int k0 = 0; k0 < K; k0 += BK) {
        bool has_next = (k0 + BK < K);
        if (has_next) {
            a = *(const float4*)&A[(bm + arow) * K + k0 + BK + acol4];
            b = *(const float4*)&W[(k0 + BK + brow) * N + bn + bcol4];
        }

        #pragma unroll
        for (int kk = 0; kk < BK; kk++) {
            float ar[TM], br[TN];
            #pragma unroll
            for (int i = 0; i < TM; i++) ar[i] = As[buf][kk][ty * TM + i];
            #pragma unroll
            for (int j = 0; j < TN; j++) br[j] = Bs[buf][kk][tx * TN + j];
            #pragma unroll
            for (int i = 0; i < TM; i++)
                #pragma unroll
                for (int j = 0; j < TN; j++)
                    acc[i][j] = fmaf(ar[i], br[j], acc[i][j]);
        }

        if (has_next) {
            int nb = buf ^ 1;
            As[nb][acol4 + 0][arow] = a.x;
            As[nb][acol4 + 1][arow] = a.y;
            As[nb][acol4 + 2][arow] = a.z;
            As[nb][acol4 + 3][arow] = a.w;
            *(float4*)&Bs[nb][brow][bcol4] = b;
            __syncthreads();
            buf = nb;
        }
    }

    #pragma unroll
    for (int i = 0; i < TM; i++) {
        int row = bm + ty * TM + i;
        #pragma unroll
        for (int j = 0; j < TN; j++) {
            int col = bn + tx * TN + j;
            float val = acc[i][j] + bias[col];
            if (residual) val += residual[row * N + col];
            C[row * N + col] = val;
        }
    }
}

// Fused QKV GEMM: blockIdx.z selects {q,k,v}.
__global__ void __launch_bounds__(256) gemm_qkv(
    const float* __restrict__ A,
    const float* __restrict__ Wq, const float* __restrict__ bq, float* __restrict__ Cq,
    const float* __restrict__ Wk, const float* __restrict__ bk, float* __restrict__ Ck,
    const float* __restrict__ Wv, const float* __restrict__ bv, float* __restrict__ Cv)
{
    const float* W; const float* bias; float* C;
    if (blockIdx.z == 0)      { W = Wq; bias = bq; C = Cq; }
    else if (blockIdx.z == 1) { W = Wk; bias = bk; C = Ck; }
    else                      { W = Wv; bias = bv; C = Cv; }
    gemm_tile_db(A, W, bias, nullptr, C, blockIdx.y * BM, blockIdx.x * BN);
}

__global__ void __launch_bounds__(256) gemm_out(
    const float* __restrict__ A,
    const float* __restrict__ W,
    const float* __restrict__ bias,
    const float* __restrict__ residual,
    float* __restrict__ C)
{
    gemm_tile_db(A, W, bias, residual, C, blockIdx.y * BM, blockIdx.x * BN);
}

// ---------------- Block-diagonal attention ----------------
// grid (NGRAPH, HEADS, 2): 2 query-halves per (graph, head). 128 threads,
// thread = one query row. K/V staged in shared. Scores computed in chunks of
// KCH=8 per thread; softmax rescale amortized once per chunk.
#define CHUNK 128
#define KCH 8

__global__ void __launch_bounds__(128) attn_kernel(
    const float* __restrict__ q,
    const float* __restrict__ k,
    const float* __restrict__ v,
    const int* __restrict__ batch,
    float* __restrict__ out)
{
    __shared__ float sK[CHUNK][HEAD_DIM];
    __shared__ float sV[CHUNK][HEAD_DIM];
    __shared__ int sBounds[2];

    int g = blockIdx.x;      // graph id
    int h = blockIdx.y;      // head
    int half = blockIdx.z;   // query half
    int t = threadIdx.x;     // 0..127

    if (t == 0) {
        int lo = 0, hi = NROWS;
        while (lo < hi) { int mid = (lo + hi) >> 1; if (batch[mid] <  g) lo = mid + 1; else hi = mid; }
        sBounds[0] = lo;
        int lo2 = lo; hi = NROWS;
        while (lo2 < hi) { int mid = (lo2 + hi) >> 1; if (batch[mid] <= g) lo2 = mid + 1; else hi = mid; }
        sBounds[1] = lo2;
    }
    __syncthreads();
    int s0 = sBounds[0], e0 = sBounds[1];
    if (s0 >= e0) return;    // graph id absent

    int hbase = h * HEAD_DIM;

    for (int q0 = s0 + half * 128; q0 < e0; q0 += 256) {
        int qi = q0 + t;
        bool active = (qi < e0);

        float4 qv[8];
        if (active) {
            const float4* qp = (const float4*)(q + (size_t)qi * HIDDEN + hbase);
            #pragma unroll
            for (int i = 0; i < 8; i++) {
                float4 x4 = qp[i];
                x4.x *= SCALE; x4.y *= SCALE; x4.z *= SCALE; x4.w *= SCALE;
                qv[i] = x4;
            }
        }
        float m = -1e30f, l = 0.f;
        float4 acc[8];
        #pragma unroll
        for (int i = 0; i < 8; i++) acc[i] = make_float4(0.f, 0.f, 0.f, 0.f);

        for (int c0 = s0; c0 < e0; c0 += CHUNK) {
            int cn = min(CHUNK, e0 - c0);
            __syncthreads();
            for (int idx = t; idx < cn * 8; idx += 128) {
                int row = idx >> 3, c4 = idx & 7;
                size_t goff = (size_t)(c0 + row) * HIDDEN + hbase + c4 * 4;
                ((float4*)sK[row])[c4] = *(const float4*)(k + goff);
                ((float4*)sV[row])[c4] = *(const float4*)(v + goff);
            }
            __syncthreads();

            if (active) {
                for (int j0 = 0; j0 < cn; j0 += KCH) {
                    // 1) scores for KCH keys into registers + chunk max
                    float sc[KCH];
                    float cmax = -3e38f;
                    #pragma unroll
                    for (int jj = 0; jj < KCH; jj++) {
                        int j = j0 + jj;
                        float s;
                        if (j < cn) {               // uniform branch
                            const float4* kr = (const float4*)sK[j];
                            float p0 = 0.f, p1 = 0.f, p2 = 0.f, p3 = 0.f;
                            #pragma unroll
                            for (int i = 0; i < 8; i++) {
                                float4 k4 = kr[i];
                                p0 = fmaf(qv[i].x, k4.x, p0);
                                p1 = fmaf(qv[i].y, k4.y, p1);
                                p2 = fmaf(qv[i].z, k4.z, p2);
                                p3 = fmaf(qv[i].w, k4.w, p3);
                            }
                            s = (p0 + p1) + (p2 + p3);
                        } else {
                            s = -3e38f;             // padded -> exp() == 0
                        }
                        sc[jj] = s;
                        cmax = fmaxf(cmax, s);
                    }
                    // 2) rescale once per chunk (rare after warm-up)
                    if (cmax > m) {
                        float co = __expf(m - cmax);
                        l *= co;
                        #pragma unroll
                        for (int i = 0; i < 8; i++) {
                            acc[i].x *= co; acc[i].y *= co;
                            acc[i].z *= co; acc[i].w *= co;
                        }
                        m = cmax;
                    }
                    // 3) exp + accumulate
                    #pragma unroll
                    for (int jj = 0; jj < KCH; jj++) {
                        float p = __expf(sc[jj] - m);
                        l += p;
                        const float4* vr = (const float4*)sV[j0 + jj];
                        #pragma unroll
                        for (int i = 0; i < 8; i++) {
                            float4 v4 = vr[i];
                            acc[i].x = fmaf(p, v4.x, acc[i].x);
                            acc[i].y = fmaf(p, v4.y, acc[i].y);
                            acc[i].z = fmaf(p, v4.z, acc[i].z);
                            acc[i].w = fmaf(p, v4.w, acc[i].w);
                        }
                    }
                }
            }
        }

        if (active) {
            float inv = 1.f / l;
            float4* op = (float4*)(out + (size_t)qi * HIDDEN + hbase);
            #pragma unroll
            for (int i = 0; i < 8; i++) {
                float4 a4 = acc[i];
                a4.x *= inv; a4.y *= inv; a4.z *= inv; a4.w *= inv;
                op[i] = a4;
            }
        }
    }
}

// ---------------- launch ----------------
extern "C" void kernel_launch(void* const* d_in, const int* in_sizes, int n_in,
                              void* d_out, int out_size)
{
    const float* x     = (const float*)d_in[0];
    const int*   batch = (const int*)d_in[1];   // int32 (JAX x64 disabled)
    const float* Wq = (const float*)d_in[2];
    const float* bq = (const float*)d_in[3];
    const float* Wk = (const float*)d_in[4];
    const float* bk = (const float*)d_in[5];
    const float* Wv = (const float*)d_in[6];
    const float* bv = (const float*)d_in[7];
    const float* Wo = (const float*)d_in[8];
    const float* bo = (const float*)d_in[9];
    const float* gamma = (const float*)d_in[10];
    const float* beta  = (const float*)d_in[11];
    float* out = (float*)d_out;

    float *h_p, *q_p, *k_p, *v_p, *att_p;
    cudaGetSymbolAddress((void**)&h_p,  g_h);
    cudaGetSymbolAddress((void**)&q_p,  g_q);
    cudaGetSymbolAddress((void**)&k_p,  g_k);
    cudaGetSymbolAddress((void**)&v_p,  g_v);
    cudaGetSymbolAddress((void**)&att_p, g_att);

    ln_kernel<<<NROWS, 256>>>(x, gamma, beta, h_p);

    dim3 gqkv(HIDDEN / BN, NROWS / BM, 3);
    gemm_qkv<<<gqkv, 256>>>(h_p, Wq, bq, q_p, Wk, bk, k_p, Wv, bv, v_p);

    dim3 ga(NGRAPH, HEADS, 2);
    attn_kernel<<<ga, 128>>>(q_p, k_p, v_p, batch, att_p);

    dim3 gg(HIDDEN / BN, NROWS / BM);
    gemm_out<<<gg, 256>>>(att_p, Wo, bo, x, out);
}